// round 16
// baseline (speedup 1.0000x reference)
#include <cuda_runtime.h>
#include <cuda_bf16.h>

// Problem constants (fixed by the reference)
#define WF 512.0f
#define HF 512.0f
#define NGMAX 2048
#define TILES_X 32
#define TILES_Y 32
#define TILES (TILES_X * TILES_Y)
#define TILE_W 16.0f
#define PCAP 256              // per-tile pixel capacity (mean 64, max ~110)
#define MWORDS 64             // 2048 bits per tile mask
#define SCAP 320              // staged coefficients (observed max well below)
#define TPB_PREP 256
#define TPB_SPLAT 128

// Per-gaussian packed coefficients: 2 x float4: [P,Q,R,mx] [my,cr,cg,cb]
// (P,Q,R pre-scaled by -log2(e) so exp is a single ex2)
__device__ float4 g_coef[NGMAX * 2];
// Per-tile gaussian bitmask (2048 bits). atomicOr is commutative+idempotent
// -> deterministic. Statically zero; splat re-zeroes after reading.
__device__ unsigned g_gmask[TILES * MWORDS];
__device__ int g_pcnt[TILES];             // statically zero; re-zeroed by splat
__device__ float4 g_pxyi[TILES * PCAP];   // [x, y, bitcast(pixel idx), 0]

__device__ __forceinline__ float ex2(float x) {
    float r; asm("ex2.approx.ftz.f32 %0,%1;" : "=f"(r) : "f"(x)); return r;
}
__device__ __forceinline__ float rcp(float x) {
    float r; asm("rcp.approx.ftz.f32 %0,%1;" : "=f"(r) : "f"(x)); return r;
}
__device__ __forceinline__ float fexp(float x) { return ex2(x * 1.4426950408889634f); }
__device__ __forceinline__ float ftanh(float x) {
    float e = ex2(x * 2.8853900817779268f);   // e^{2x}
    return 1.0f - 2.0f * rcp(e + 1.0f);
}
__device__ __forceinline__ float fsigm(float x) {
    return rcp(1.0f + fexp(-x));
}

// ---------------------------------------------------------------------------
// Kernel 1: warp w owns gaussian w (lane-parallel tile-box binning kills the
// big-gaussian straggler); every thread bins exactly 1 pixel.
// Calls cudaTriggerProgrammaticLaunchCompletion() early: all 256 prep blocks
// are wave-1 resident, so early-launched splat blocks cannot starve them;
// memory visibility is enforced by splat's cudaGridDependencySynchronize().
// Cull: |v| > 4/minS gives w < e^-16; dropped mass <= 2048*1.1e-7 ~ 2e-4 abs.
// ---------------------------------------------------------------------------
__global__ void __launch_bounds__(TPB_PREP) prep_kernel(const float* __restrict__ rgb,
                                                        const float* __restrict__ mu,
                                                        const float* __restrict__ scale,
                                                        const float* __restrict__ angle,
                                                        const float* __restrict__ x,
                                                        int N, int B) {
    cudaTriggerProgrammaticLaunchCompletion();

    int gtid = blockIdx.x * TPB_PREP + threadIdx.x;
    int gi   = gtid >> 5;          // gaussian owned by this warp
    int lane = gtid & 31;

    // pixel-binning load issued FIRST (independent of everything below)
    float2 xy = make_float2(0.f, 0.f);
    if (gtid < B) xy = ((const float2*)x)[gtid];

    if (gi < N) {
        const float MU_BORDER = 1.05f;
        const float PI_APPROX = 3.1416f;
        const float S_MIN = 1.0f / 30.0f;
        const float S_MAX = 1.0f / 0.75f;
        const float LOG2E = 1.4426950408889634f;

        // warp-uniform loads (broadcast), redundantly computed by all lanes
        float mpx = (ftanh(mu[2 * gi + 0]) * MU_BORDER + 1.0f) * 0.5f * WF;
        float mpy = (ftanh(mu[2 * gi + 1]) * MU_BORDER + 1.0f) * 0.5f * HF;

        float al = ftanh(angle[gi]) * PI_APPROX;
        float c, s;
        __sincosf(al, &s, &c);

        float S0 = fsigm(scale[2 * gi + 0]) * (S_MAX - S_MIN) + S_MIN;
        float S1 = fsigm(scale[2 * gi + 1]) * (S_MAX - S_MIN) + S_MIN;

        float a = S0 * c, b = -S0 * s;
        float e = S1 * s, f = S1 * c;

        float P = -LOG2E * (a * a + e * e);
        float Q = -LOG2E * 2.0f * (a * b + e * f);
        float R = -LOG2E * (b * b + f * f);

        if (lane == 0) {
            float cr = fsigm(rgb[3 * gi + 0]);
            float cg = fsigm(rgb[3 * gi + 1]);
            float cb = fsigm(rgb[3 * gi + 2]);
            g_coef[2 * gi]     = make_float4(P, Q, R, mpx);
            g_coef[2 * gi + 1] = make_float4(mpy, cr, cg, cb);
        }

        // ---- lane-parallel gaussian -> tile bitmask binning ----
        float Smin = fminf(S0, S1);
        float r = 4.0f / Smin;                 // w = e^-16 level set
        float r2 = r * r * 1.0001f + 1e-2f;

        int txmin = max(0, (int)((mpx - r) * (1.0f / TILE_W)));
        int txmax = min(TILES_X - 1, (int)((mpx + r) * (1.0f / TILE_W)));
        int tymin = max(0, (int)((mpy - r) * (1.0f / TILE_W)));
        int tymax = min(TILES_Y - 1, (int)((mpy + r) * (1.0f / TILE_W)));
        int bw = txmax - txmin + 1;
        int bh = tymax - tymin + 1;
        int nbox = bw * bh;

        unsigned bit = 1u << (gi & 31);
        int word = gi >> 5;

        for (int idx = lane; idx < nbox; idx += 32) {
            int ty = tymin + idx / bw;
            int tx = txmin + idx - (idx / bw) * bw;
            float x0 = tx * TILE_W, x1 = x0 + TILE_W;
            float y0 = ty * TILE_W, y1 = y0 + TILE_W;
            float dx = fmaxf(fmaxf(x0 - mpx, mpx - x1), 0.0f);
            float dy = fmaxf(fmaxf(y0 - mpy, mpy - y1), 0.0f);
            if (dx * dx + dy * dy <= r2) {
                atomicOr(&g_gmask[(ty * TILES_X + tx) * MWORDS + word], bit);
            }
        }
    }

    // ---- pixel binning: 1 pixel per thread; single 16B record ----
    if (gtid < B) {
        int tx = (int)(xy.x * (1.0f / TILE_W));
        int ty = (int)(xy.y * (1.0f / TILE_W));
        tx = min(max(tx, 0), TILES_X - 1);
        ty = min(max(ty, 0), TILES_Y - 1);
        int t = ty * TILES_X + tx;
        int slot = atomicAdd(&g_pcnt[t], 1);
        if (slot < PCAP) {
            g_pxyi[t * PCAP + slot] =
                make_float4(xy.x, xy.y, __int_as_float(gtid), 0.0f);
        }
    }
}

// ---------------------------------------------------------------------------
// Kernel 2: per-tile splat, 1024 blocks x 128 threads, launched with
// programmatic stream serialization (PDL): blocks are scheduled during prep
// and park at cudaGridDependencySynchronize(). After the sync, pcnt / pixel
// record / mask word are THREE PARALLEL L2 round trips (px0 loaded
// unconditionally; stale slots are loaded but only consumed if tid < pcnt).
// Threads 0-63 expand the bitmask in ASCENDING INDEX ORDER (deterministic),
// all 128 gather coefficients, pixels run fully parallel.
// Re-zeroes g_gmask and g_pcnt for the next graph replay.
// ---------------------------------------------------------------------------
__global__ void __launch_bounds__(TPB_SPLAT) splat_tiled(float* __restrict__ out) {
    __shared__ unsigned short slist[NGMAX];   // 4 KB (full-safety capacity)
    __shared__ float4 scoef[SCAP][2];         // 10 KB
    __shared__ int wtot[2];

    const int t = blockIdx.x;
    const int tid = threadIdx.x;
    const int wid = tid >> 5;
    const int lane = tid & 31;

    cudaGridDependencySynchronize();          // wait for prep's memory

    // ---- three independent loads (max MLP, no predication chain) ----
    const int pcnt_raw = g_pcnt[t];
    float4 px0 = g_pxyi[t * PCAP + tid];      // unconditional; gated by pcnt later
    unsigned m = 0;
    if (tid < MWORDS) {
        m = g_gmask[t * MWORDS + tid];
        g_gmask[t * MWORDS + tid] = 0;        // reset for next graph replay
    }
    const int pcnt = min(pcnt_raw, PCAP);

    // ---- build gaussian list (threads 0-63; ascending index order) ----
    int c = __popc(m);
    int inc = c;
#pragma unroll
    for (int d = 1; d < 32; d <<= 1) {
        int v = __shfl_up_sync(0xffffffffu, inc, d);
        if (lane >= d) inc += v;
    }
    if (wid < 2 && lane == 31) wtot[wid] = inc;
    __syncthreads();
    const int total = wtot[0] + wtot[1];

    if (tid < MWORDS) {
        int off = inc - c + (wid ? wtot[0] : 0);
        unsigned mm = m;
        int o = off;
        int base = tid * 32;
        while (mm) {
            int b = __ffs(mm) - 1;
            slist[o++] = (unsigned short)(base + b);
            mm &= mm - 1;
        }
    }
    __syncthreads();

    // ---- cooperative coefficient staging (full-MLP gather) ----
    const int nc = min(total, SCAP);
    for (int j = tid; j < nc; j += TPB_SPLAT) {
        int gi = slist[j];
        scoef[j][0] = g_coef[2 * gi];
        scoef[j][1] = g_coef[2 * gi + 1];
    }
    if (tid == 0) g_pcnt[t] = 0;              // reset for next graph replay
    __syncthreads();

    // ---- pixel loop: pcnt <= ~110 < 128 -> normally ONE iteration ----
    for (int i = tid; i < pcnt; i += TPB_SPLAT) {
        float4 rec = (i == tid) ? px0 : g_pxyi[t * PCAP + i];
        float px = rec.x, py = rec.y;

        float ar = 0.f, ag = 0.f, ab = 0.f;

#pragma unroll 4
        for (int j = 0; j < nc; j++) {
            float4 cA = scoef[j][0];          // P,Q,R,mx
            float4 cB = scoef[j][1];          // my,cr,cg,cb
            float vx = px - cA.w;
            float vy = py - cB.x;
            float q = fmaf(vx, fmaf(cA.y, vy, cA.x * vx), (cA.z * vy) * vy);
            float wgt = ex2(q);
            ar = fmaf(wgt, cB.y, ar);
            ag = fmaf(wgt, cB.z, ag);
            ab = fmaf(wgt, cB.w, ab);
        }
        // overflow path (statistically never; preserves correctness)
        for (int j = SCAP; j < total; j++) {
            int gi = slist[j];
            float4 cA = g_coef[2 * gi];
            float4 cB = g_coef[2 * gi + 1];
            float vx = px - cA.w;
            float vy = py - cB.x;
            float q = fmaf(vx, fmaf(cA.y, vy, cA.x * vx), (cA.z * vy) * vy);
            float wgt = ex2(q);
            ar = fmaf(wgt, cB.y, ar);
            ag = fmaf(wgt, cB.z, ag);
            ab = fmaf(wgt, cB.w, ab);
        }

        int pix = __float_as_int(rec.z);
        out[3 * pix + 0] = ar;
        out[3 * pix + 1] = ag;
        out[3 * pix + 2] = ab;
    }
}

// ---------------------------------------------------------------------------
// Launch: inputs in metadata order: x[B,2], rgb[N,3], mu[N,2], scale[N,2], angle[N]
// splat is launched with the PDL attribute so its blocks schedule during prep.
// ---------------------------------------------------------------------------
extern "C" void kernel_launch(void* const* d_in, const int* in_sizes, int n_in,
                              void* d_out, int out_size) {
    const float* x     = (const float*)d_in[0];
    const float* rgb   = (const float*)d_in[1];
    const float* mu    = (const float*)d_in[2];
    const float* scale = (const float*)d_in[3];
    const float* angle = (const float*)d_in[4];
    float* out = (float*)d_out;

    int N = in_sizes[4];          // 2048
    int B = in_sizes[0] / 2;      // 65536

    prep_kernel<<<B / TPB_PREP, TPB_PREP>>>(rgb, mu, scale, angle, x, N, B);

    cudaLaunchConfig_t cfg = {};
    cfg.gridDim = dim3(TILES);
    cfg.blockDim = dim3(TPB_SPLAT);
    cudaLaunchAttribute attrs[1];
    attrs[0].id = cudaLaunchAttributeProgrammaticStreamSerialization;
    attrs[0].val.programmaticStreamSerializationAllowed = 1;
    cfg.attrs = attrs;
    cfg.numAttrs = 1;
    cudaLaunchKernelEx(&cfg, splat_tiled, out);
}